// round 1
// baseline (speedup 1.0000x reference)
#include <cuda_runtime.h>
#include <cstdint>

// Problem constants
#define NB 8
#define NL 2048
#define ND 128
#define EPSN 1e-8f

// ---------------- scratch (no allocation allowed) ----------------
__device__ float g_cn[NB * NL * ND];   // normalized ctx  (8 MB)
__device__ float g_en[NB * NL * ND];   // normalized ent  (8 MB)
__device__ int   g_idx[NB * NL];       // argmax indices

// =================================================================
// Stage 1: L2-normalize both halves of context.
// One warp per row (128 floats = 32 lanes x float4).
// =================================================================
__global__ void norm_kernel(const float* __restrict__ ctx) {
    int gwarp = (blockIdx.x * blockDim.x + threadIdx.x) >> 5;
    int lane  = threadIdx.x & 31;
    if (gwarp >= 2 * NB * NL) return;
    int which = gwarp >> 14;          // 0 -> cn, 1 -> en
    int r     = gwarp & (NB * NL - 1);
    int b = r >> 11, l = r & (NL - 1);
    const float4* src =
        (const float4*)(ctx + ((size_t)(b * 2 + which) * NL + l) * ND);
    float4 v = src[lane];
    float s = v.x * v.x + v.y * v.y + v.z * v.z + v.w * v.w;
#pragma unroll
    for (int o = 16; o; o >>= 1) s += __shfl_xor_sync(0xffffffffu, s, o);
    float n   = sqrtf(s);
    float inv = 1.0f / fmaxf(n, EPSN);
    float4 o4 = make_float4(v.x * inv, v.y * inv, v.z * inv, v.w * inv);
    float* dst = which ? g_en : g_cn;
    ((float4*)(dst + (size_t)r * ND))[lane] = o4;
}

// =================================================================
// Stage 2: fused sim-GEMM + row argmax.
// Block tile: 64 l-rows x 128 m-cols, 128 threads, 8x8 per thread.
// smem k-major with padded strides (float4-aligned: 68, 132).
// Each thread keeps a running (max, idx) for its 8 l-rows across
// all m tiles; block-level reduce at the end.
// =================================================================
#define BL  64
#define BM  128
#define CNS 68
#define ENS 132

__global__ __launch_bounds__(128, 2) void argmax_kernel() {
    extern __shared__ float sm[];
    float* cnT = sm;                 // [128][CNS]
    float* enT = sm + 128 * CNS;     // [128][ENS]

    int tid = threadIdx.x;
    int tx  = tid & 15;              // m sub-tile
    int ty  = tid >> 4;              // l sub-tile
    int b   = blockIdx.y;
    int l0  = blockIdx.x * BL;

    const float* cnG = g_cn + ((size_t)b * NL + l0) * ND;
    const float* enG = g_en + (size_t)b * NL * ND;

    // fill cn tile (transposed, once per block)
#pragma unroll
    for (int i = 0; i < (BL * ND) / 128; ++i) {   // 64 iters
        int flat = i * 128 + tid;
        int k = flat & 127, l = flat >> 7;
        cnT[k * CNS + l] = cnG[l * ND + k];
    }

    float bestv[8];
    int   besti[8];
#pragma unroll
    for (int i = 0; i < 8; ++i) { bestv[i] = -2.0f; besti[i] = 0; }

    for (int mb = 0; mb < NL; mb += BM) {
        __syncthreads();
        // fill en tile (transposed)
#pragma unroll
        for (int i = 0; i < (BM * ND) / 128; ++i) {  // 128 iters
            int flat = i * 128 + tid;
            int k = flat & 127, m = flat >> 7;
            enT[k * ENS + m] = enG[(size_t)(mb + m) * ND + k];
        }
        __syncthreads();

        float acc[8][8];
#pragma unroll
        for (int i = 0; i < 8; ++i)
#pragma unroll
            for (int j = 0; j < 8; ++j) acc[i][j] = 0.0f;

#pragma unroll 4
        for (int k = 0; k < ND; ++k) {
            // l rows: ty*4+i (i<4) and 32+ty*4+(i-4)  -> conflict-free
            float4 a0 = *(const float4*)(cnT + k * CNS + ty * 4);
            float4 a1 = *(const float4*)(cnT + k * CNS + 32 + ty * 4);
            // m cols: tx*4+j (j<4) and 64+tx*4+(j-4)  -> conflict-free
            float4 b0 = *(const float4*)(enT + k * ENS + tx * 4);
            float4 b1 = *(const float4*)(enT + k * ENS + 64 + tx * 4);
            float av[8] = {a0.x, a0.y, a0.z, a0.w, a1.x, a1.y, a1.z, a1.w};
            float bv[8] = {b0.x, b0.y, b0.z, b0.w, b1.x, b1.y, b1.z, b1.w};
#pragma unroll
            for (int i = 0; i < 8; ++i)
#pragma unroll
                for (int j = 0; j < 8; ++j) acc[i][j] += av[i] * bv[j];
        }

        // update running argmax (first-occurrence tie-break)
#pragma unroll
        for (int i = 0; i < 8; ++i)
#pragma unroll
            for (int j = 0; j < 8; ++j) {
                int m = mb + ((j < 4) ? (tx * 4 + j) : (64 + tx * 4 + (j - 4)));
                float v = acc[i][j];
                if (v > bestv[i] || (v == bestv[i] && m < besti[i])) {
                    bestv[i] = v;
                    besti[i] = m;
                }
            }
    }

    __syncthreads();
    // block reduce: 16 tx-threads per l-row
    float* redv = sm;                   // [64][16]
    int*   redi = (int*)(sm + 1024);    // [64][16]
#pragma unroll
    for (int i = 0; i < 8; ++i) {
        int ll = (i < 4) ? (ty * 4 + i) : (32 + ty * 4 + (i - 4));
        redv[ll * 16 + tx] = bestv[i];
        redi[ll * 16 + tx] = besti[i];
    }
    __syncthreads();
    if (tid < 64) {
        float bv = redv[tid * 16];
        int   bi = redi[tid * 16];
        for (int t = 1; t < 16; ++t) {
            float v  = redv[tid * 16 + t];
            int   ix = redi[tid * 16 + t];
            if (v > bv || (v == bv && ix < bi)) { bv = v; bi = ix; }
        }
        g_idx[b * NL + l0 + tid] = bi;
    }
}

// =================================================================
// Stage 3: per-token 2-row MLP + reduction.
// Block: 128 threads (thread j owns output neuron j), 64 tokens per
// block in groups of 8 (16 row-vectors live in smem, W1 transposed
// in smem loaded once per block).
// out[tok] = sum_j relu(cn.W1[:,j]+b1_j)W2_j
//          + sum_j relu(matched.W1[:,j]+b1_j)W2_j + 2*b2
// =================================================================
#define W1S 132

__global__ __launch_bounds__(128) void mlp_kernel(
    const float* __restrict__ W1, const float* __restrict__ b1,
    const float* __restrict__ W2, const float* __restrict__ b2,
    float* __restrict__ out) {
    extern __shared__ float sm[];
    float* W1t  = sm;                        // [128][W1S]  W1t[j][k] = W1[k][j]
    float* rows = sm + 128 * W1S;            // [16][128]
    float* part = sm + 128 * W1S + 16 * 128; // [8][4] per-token warp partials

    int tid  = threadIdx.x;
    int lane = tid & 31;
    int wp   = tid >> 5;

    // load W1 transposed (coalesced global reads)
#pragma unroll
    for (int i = 0; i < 128; ++i) {
        int flat = i * 128 + tid;
        int j = flat & 127, k = flat >> 7;
        W1t[j * W1S + k] = W1[k * 128 + j];
    }
    float bias = b1[tid];
    float w2   = W2[tid];
    float bb2  = b2[0];

    int tok0 = blockIdx.x * 64;
    for (int g0 = 0; g0 < 64; g0 += 8) {
        __syncthreads();
        // gather 16 row vectors: even r = cn, odd r = matched en
#pragma unroll
        for (int i = 0; i < 16; ++i) {
            int flat = i * 128 + tid;
            int r = flat >> 7, k = flat & 127;
            int tok = tok0 + g0 + (r >> 1);
            const float* src;
            if (r & 1) {
                int bb = tok >> 11;
                int mi = g_idx[tok];
                src = g_en + ((size_t)(bb << 11) + mi) * ND;
            } else {
                src = g_cn + (size_t)tok * ND;
            }
            rows[r * 128 + k] = src[k];
        }
        __syncthreads();

        float acc[16];
#pragma unroll
        for (int r = 0; r < 16; ++r) acc[r] = bias;

#pragma unroll 4
        for (int kq = 0; kq < 32; ++kq) {
            float4 w = *(const float4*)(W1t + tid * W1S + kq * 4);
#pragma unroll
            for (int r = 0; r < 16; ++r) {
                float4 x = *(const float4*)(rows + r * 128 + kq * 4);
                acc[r] += w.x * x.x + w.y * x.y + w.z * x.z + w.w * x.w;
            }
        }

        // combine the 2 rows of each token, then reduce over the 128 j's
        float c[8];
#pragma unroll
        for (int g = 0; g < 8; ++g) {
            float h0 = fmaxf(acc[2 * g], 0.0f);
            float h1 = fmaxf(acc[2 * g + 1], 0.0f);
            c[g] = (h0 + h1) * w2;
        }
#pragma unroll
        for (int g = 0; g < 8; ++g) {
            float v = c[g];
#pragma unroll
            for (int o = 16; o; o >>= 1) v += __shfl_xor_sync(0xffffffffu, v, o);
            c[g] = v;
        }
        if (lane == 0) {
#pragma unroll
            for (int g = 0; g < 8; ++g) part[g * 4 + wp] = c[g];
        }
        __syncthreads();
        if (tid < 8) {
            float s = part[tid * 4] + part[tid * 4 + 1] +
                      part[tid * 4 + 2] + part[tid * 4 + 3];
            out[tok0 + g0 + tid] = s + 2.0f * bb2;
        }
    }
}

// =================================================================
// launch
// =================================================================
extern "C" void kernel_launch(void* const* d_in, const int* in_sizes, int n_in,
                              void* d_out, int out_size) {
    const float* context = (const float*)d_in[0];
    const float* W1      = (const float*)d_in[1];
    const float* b1      = (const float*)d_in[2];
    const float* W2      = (const float*)d_in[3];
    const float* b2      = (const float*)d_in[4];
    float* out           = (float*)d_out;

    // Stage 1: 32768 warps
    {
        int warps = 2 * NB * NL;
        int threads = 256;
        int blocks = (warps * 32 + threads - 1) / threads;
        norm_kernel<<<blocks, threads>>>(context);
    }

    // Stage 2: fused sim + argmax
    {
        size_t smem = (size_t)(128 * CNS + 128 * ENS) * sizeof(float); // 102400 B
        cudaFuncSetAttribute(argmax_kernel,
                             cudaFuncAttributeMaxDynamicSharedMemorySize,
                             (int)smem);
        dim3 grid(NL / BL, NB);
        argmax_kernel<<<grid, 128, smem>>>();
    }

    // Stage 3: MLP
    {
        size_t smem = (size_t)(128 * W1S + 16 * 128 + 64) * sizeof(float); // 76 KB
        cudaFuncSetAttribute(mlp_kernel,
                             cudaFuncAttributeMaxDynamicSharedMemorySize,
                             (int)smem);
        mlp_kernel<<<NB * NL / 64, 128, smem>>>(W1, b1, W2, b2, out);
    }
}

// round 3
// speedup vs baseline: 1.8988x; 1.8988x over previous
#include <cuda_runtime.h>
#include <cuda_bf16.h>
#include <cstdint>

// Problem constants
#define NB 8
#define NL 2048
#define ND 128
#define EPSN 1e-8f
#define MARGIN 0.02f
#define CCAP 48

// ---------------- scratch (no allocation allowed) ----------------
__device__ float g_cn[NB * NL * ND];               // normalized ctx (fp32)
__device__ float g_en[NB * NL * ND];               // normalized ent (fp32)
__device__ __nv_bfloat16 g_cnbf[NB * NL * ND];     // bf16(cn)
__device__ __nv_bfloat16 g_enbf[NB * NL * ND];     // bf16(en)
__device__ int g_idx[NB * NL];

// ---------------- PTX helpers (compute_103-safe) ----------------
__device__ __forceinline__ uint32_t smem_u32(const void* p) {
    uint32_t a;
    asm("{ .reg .u64 t; cvta.to.shared.u64 t, %1; cvt.u32.u64 %0, t; }"
        : "=r"(a) : "l"(p));
    return a;
}
__device__ __forceinline__ void ldmA(uint32_t* a, uint32_t addr) {
    asm volatile("ldmatrix.sync.aligned.m8n8.x4.shared.b16 {%0,%1,%2,%3}, [%4];"
                 : "=r"(a[0]), "=r"(a[1]), "=r"(a[2]), "=r"(a[3]) : "r"(addr));
}
__device__ __forceinline__ void ldmB(uint32_t* b, uint32_t addr) {
    asm volatile("ldmatrix.sync.aligned.m8n8.x2.shared.b16 {%0,%1}, [%2];"
                 : "=r"(b[0]), "=r"(b[1]) : "r"(addr));
}
__device__ __forceinline__ void mma16816(float* c, const uint32_t* a,
                                         const uint32_t* b) {
    asm volatile(
        "mma.sync.aligned.m16n8k16.row.col.f32.bf16.bf16.f32 "
        "{%0,%1,%2,%3}, {%4,%5,%6,%7}, {%8,%9}, {%0,%1,%2,%3};"
        : "+f"(c[0]), "+f"(c[1]), "+f"(c[2]), "+f"(c[3])
        : "r"(a[0]), "r"(a[1]), "r"(a[2]), "r"(a[3]), "r"(b[0]), "r"(b[1]));
}
#define CP_ASYNC16(dst, src) \
    asm volatile("cp.async.cg.shared.global [%0], [%1], 16;" :: "r"(dst), "l"(src))
#define CP_COMMIT() asm volatile("cp.async.commit_group;")
#define CP_WAIT(n)  asm volatile("cp.async.wait_group %0;" :: "n"(n))

// =================================================================
// Stage 1: L2-normalize; emit fp32 rows + bf16 rows.
// =================================================================
__global__ void norm_kernel2(const float* __restrict__ ctx) {
    int gwarp = (blockIdx.x * blockDim.x + threadIdx.x) >> 5;
    int lane  = threadIdx.x & 31;
    if (gwarp >= 2 * NB * NL) return;
    int which = gwarp >> 14;
    int r     = gwarp & (NB * NL - 1);
    int b = r >> 11, l = r & (NL - 1);
    const float4* src =
        (const float4*)(ctx + ((size_t)(b * 2 + which) * NL + l) * ND);
    float4 v = src[lane];
    float s = v.x * v.x + v.y * v.y + v.z * v.z + v.w * v.w;
#pragma unroll
    for (int o = 16; o; o >>= 1) s += __shfl_xor_sync(0xffffffffu, s, o);
    float inv = 1.0f / fmaxf(sqrtf(s), EPSN);
    float4 o4 = make_float4(v.x * inv, v.y * inv, v.z * inv, v.w * inv);
    float* dst = which ? g_en : g_cn;
    ((float4*)(dst + (size_t)r * ND))[lane] = o4;

    __nv_bfloat16* bdst = which ? g_enbf : g_cnbf;
    __nv_bfloat162* hp = (__nv_bfloat162*)(bdst + (size_t)r * ND + lane * 4);
    hp[0] = __halves2bfloat162(__float2bfloat16(o4.x), __float2bfloat16(o4.y));
    hp[1] = __halves2bfloat162(__float2bfloat16(o4.z), __float2bfloat16(o4.w));
}

// =================================================================
// Stage 2: HMMA sim-GEMM + fused argmax with candidate rescore.
// CTA: 128 l-rows, 256 threads (8 warps, 4x2 warp grid, 32x64 tiles).
// =================================================================
#define SM_AT   0
#define SM_BT0  34816
#define SM_BT1  69632
#define SM_CV   104448
#define SM_CI   129024
#define SM_CNT  153600
#define SM_HM   154112
#define SM_SIM_TOTAL 155136
#define LDH 136
#define LDB 272

__global__ __launch_bounds__(256, 1) void simarg_kernel() {
    extern __shared__ char smc[];
    float* candV = (float*)(smc + SM_CV);
    int*   candI = (int*)(smc + SM_CI);
    int*   cnt   = (int*)(smc + SM_CNT);
    float* hmax  = (float*)(smc + SM_HM);

    int tid = threadIdx.x, w = tid >> 5, lane = tid & 31;
    int wy = w >> 1, wx = w & 1;
    int g = lane >> 2, t = lane & 3;
    int b = blockIdx.y, l0 = blockIdx.x * 128;

    if (tid < 128) cnt[tid] = 0;

    // load A tile (plain vectorized copy)
    const uint4* asrc = (const uint4*)(g_cnbf + ((size_t)b * NL + l0) * ND);
#pragma unroll
    for (int i = tid; i < 2048; i += 256) {
        int row = i >> 4, c = i & 15;
        *(uint4*)(smc + SM_AT + row * LDB + c * 16) = asrc[row * 16 + c];
    }

    const char* esrc = (const char*)(g_enbf + (size_t)b * NL * ND);
    uint32_t sb = smem_u32(smc);

    // prefetch B tile 0
#pragma unroll
    for (int i = tid; i < 2048; i += 256) {
        int row = i >> 4, c = i & 15;
        CP_ASYNC16(sb + SM_BT0 + row * LDB + c * 16,
                   esrc + (size_t)row * 256 + c * 16);
    }
    CP_COMMIT();

    uint32_t aaddr = sb + SM_AT + ((32 * wy + (lane & 15)) * LDB + (lane >> 4) * 16);
    uint32_t baddr0 = ((lane & 7)) * LDB + ((lane >> 3) & 1) * 16;

    float rmax[2][2] = {{-2.0f, -2.0f}, {-2.0f, -2.0f}};

    for (int mt = 0; mt < 16; ++mt) {
        int cur = mt & 1;
        if (mt + 1 < 16) {
            int nb_ = SM_BT0 + ((mt + 1) & 1) * 34816;
#pragma unroll
            for (int i = tid; i < 2048; i += 256) {
                int row = i >> 4, c = i & 15;
                CP_ASYNC16(sb + nb_ + row * LDB + c * 16,
                           esrc + ((size_t)(mt + 1) * 128 + row) * 256 + c * 16);
            }
            CP_COMMIT();
            CP_WAIT(1);
        } else {
            CP_WAIT(0);
        }
        __syncthreads();

        uint32_t bbase = sb + SM_BT0 + cur * 34816 + baddr0 + wx * 64 * LDB;

        float acc[2][8][4];
#pragma unroll
        for (int f = 0; f < 2; ++f)
#pragma unroll
            for (int j = 0; j < 8; ++j)
#pragma unroll
                for (int c = 0; c < 4; ++c) acc[f][j][c] = 0.0f;

#pragma unroll
        for (int kc = 0; kc < 8; ++kc) {
            uint32_t a0[4], a1[4];
            ldmA(a0, aaddr + kc * 32);
            ldmA(a1, aaddr + 16 * LDB + kc * 32);
#pragma unroll
            for (int j = 0; j < 8; ++j) {
                uint32_t bb[2];
                ldmB(bb, bbase + j * 8 * LDB + kc * 32);
                mma16816(acc[0][j], a0, bb);
                mma16816(acc[1][j], a1, bb);
            }
        }

        // epilogue: running max + candidate append
#pragma unroll
        for (int f = 0; f < 2; ++f)
#pragma unroll
            for (int h = 0; h < 2; ++h) {
                float tm = -2.0f;
#pragma unroll
                for (int j = 0; j < 8; ++j)
                    tm = fmaxf(tm, fmaxf(acc[f][j][2 * h], acc[f][j][2 * h + 1]));
                tm = fmaxf(tm, __shfl_xor_sync(0xffffffffu, tm, 1));
                tm = fmaxf(tm, __shfl_xor_sync(0xffffffffu, tm, 2));
                float nm = fmaxf(rmax[f][h], tm);
                rmax[f][h] = nm;
                float thr = nm - MARGIN;
                int r = 32 * wy + 16 * f + 8 * h + g;
#pragma unroll
                for (int j = 0; j < 8; ++j)
#pragma unroll
                    for (int c = 0; c < 2; ++c) {
                        float v = acc[f][j][2 * h + c];
                        if (v >= thr) {
                            int pos = atomicAdd(&cnt[r], 1);
                            if (pos < CCAP) {
                                candV[r * CCAP + pos] = v;
                                candI[r * CCAP + pos] =
                                    mt * 128 + wx * 64 + j * 8 + 2 * t + c;
                            }
                        }
                    }
            }
        __syncthreads();  // done reading Bt[cur] before it is refilled
    }

    // publish per-warp-half row maxima
    if (t == 0) {
#pragma unroll
        for (int f = 0; f < 2; ++f)
#pragma unroll
            for (int h = 0; h < 2; ++h)
                hmax[(32 * wy + 16 * f + 8 * h + g) * 2 + wx] = rmax[f][h];
    }
    __syncthreads();

    // filter + exact fp32 rescore: 2 threads per row
    {
        int r = tid >> 1;
        float Mb = fmaxf(hmax[r * 2], hmax[r * 2 + 1]);
        float thr = Mb - MARGIN;
        int n = min(cnt[r], CCAP);
        float bv = -1e30f;
        int bi = 0x7fffffff;
        const float4* xa = (const float4*)(g_cn + ((size_t)b * NL + l0 + r) * ND);
        for (int e = (tid & 1); e < n; e += 2) {
            if (candV[r * CCAP + e] < thr) continue;
            int m = candI[r * CCAP + e];
            const float4* xb = (const float4*)(g_en + ((size_t)b * NL + m) * ND);
            float s0 = 0, s1 = 0, s2 = 0, s3 = 0;
#pragma unroll
            for (int q = 0; q < 32; ++q) {
                float4 A = xa[q];
                float4 Bv = xb[q];
                s0 += A.x * Bv.x; s1 += A.y * Bv.y;
                s2 += A.z * Bv.z; s3 += A.w * Bv.w;
            }
            float s = (s0 + s1) + (s2 + s3);
            if (s > bv || (s == bv && m < bi)) { bv = s; bi = m; }
        }
        __syncthreads();
        candV[tid] = bv;
        candI[tid] = bi;
        __syncthreads();
        if (tid < 128) {
            float v0 = candV[tid * 2], v1 = candV[tid * 2 + 1];
            int i0 = candI[tid * 2], i1 = candI[tid * 2 + 1];
            int best = (v1 > v0 || (v1 == v0 && i1 < i0)) ? i1 : i0;
            g_idx[b * NL + l0 + tid] = best;
        }
    }
}

// =================================================================
// Stage 3: per-token 2-row MLP + reduction (unchanged).
// =================================================================
#define W1S 132

__global__ __launch_bounds__(128) void mlp_kernel(
    const float* __restrict__ W1, const float* __restrict__ b1,
    const float* __restrict__ W2, const float* __restrict__ b2,
    float* __restrict__ out) {
    extern __shared__ float sm[];
    float* W1t  = sm;
    float* rows = sm + 128 * W1S;
    float* part = sm + 128 * W1S + 16 * 128;

    int tid  = threadIdx.x;
    int lane = tid & 31;
    int wp   = tid >> 5;

#pragma unroll
    for (int i = 0; i < 128; ++i) {
        int flat = i * 128 + tid;
        int j = flat & 127, k = flat >> 7;
        W1t[j * W1S + k] = W1[k * 128 + j];
    }
    float bias = b1[tid];
    float w2   = W2[tid];
    float bb2  = b2[0];

    int tok0 = blockIdx.x * 64;
    for (int g0 = 0; g0 < 64; g0 += 8) {
        __syncthreads();
#pragma unroll
        for (int i = 0; i < 16; ++i) {
            int flat = i * 128 + tid;
            int r = flat >> 7, k = flat & 127;
            int tok = tok0 + g0 + (r >> 1);
            const float* src;
            if (r & 1) {
                int bb = tok >> 11;
                int mi = g_idx[tok];
                src = g_en + ((size_t)(bb << 11) + mi) * ND;
            } else {
                src = g_cn + (size_t)tok * ND;
            }
            rows[r * 128 + k] = src[k];
        }
        __syncthreads();

        float acc[16];
#pragma unroll
        for (int r = 0; r < 16; ++r) acc[r] = bias;

#pragma unroll 4
        for (int kq = 0; kq < 32; ++kq) {
            float4 w4 = *(const float4*)(W1t + tid * W1S + kq * 4);
#pragma unroll
            for (int r = 0; r < 16; ++r) {
                float4 x = *(const float4*)(rows + r * 128 + kq * 4);
                acc[r] += w4.x * x.x + w4.y * x.y + w4.z * x.z + w4.w * x.w;
            }
        }

        float c[8];
#pragma unroll
        for (int g = 0; g < 8; ++g) {
            float h0 = fmaxf(acc[2 * g], 0.0f);
            float h1 = fmaxf(acc[2 * g + 1], 0.0f);
            c[g] = (h0 + h1) * w2;
        }
#pragma unroll
        for (int g = 0; g < 8; ++g) {
            float v = c[g];
#pragma unroll
            for (int o = 16; o; o >>= 1) v += __shfl_xor_sync(0xffffffffu, v, o);
            c[g] = v;
        }
        if (lane == 0) {
#pragma unroll
            for (int g = 0; g < 8; ++g) part[g * 4 + wp] = c[g];
        }
        __syncthreads();
        if (tid < 8) {
            float s = part[tid * 4] + part[tid * 4 + 1] +
                      part[tid * 4 + 2] + part[tid * 4 + 3];
            out[tok0 + g0 + tid] = s + 2.0f * bb2;
        }
    }
}

// =================================================================
// launch
// =================================================================
extern "C" void kernel_launch(void* const* d_in, const int* in_sizes, int n_in,
                              void* d_out, int out_size) {
    const float* context = (const float*)d_in[0];
    const float* W1      = (const float*)d_in[1];
    const float* b1      = (const float*)d_in[2];
    const float* W2      = (const float*)d_in[3];
    const float* b2      = (const float*)d_in[4];
    float* out           = (float*)d_out;

    {
        int warps = 2 * NB * NL;
        int threads = 256;
        int blocks = (warps * 32 + threads - 1) / threads;
        norm_kernel2<<<blocks, threads>>>(context);
    }
    {
        cudaFuncSetAttribute(simarg_kernel,
                             cudaFuncAttributeMaxDynamicSharedMemorySize,
                             SM_SIM_TOTAL);
        dim3 grid(NL / 128, NB);
        simarg_kernel<<<grid, 256, SM_SIM_TOTAL>>>();
    }
    {
        size_t smem = (size_t)(128 * W1S + 16 * 128 + 64) * sizeof(float);
        cudaFuncSetAttribute(mlp_kernel,
                             cudaFuncAttributeMaxDynamicSharedMemorySize,
                             (int)smem);
        mlp_kernel<<<NB * NL / 64, 128, smem>>>(W1, b1, W2, b2, out);
    }
}